// round 15
// baseline (speedup 1.0000x reference)
#include <cuda_runtime.h>
#include <cuda_bf16.h>
#include <cstdint>

// ---------------- problem constants ----------------
#define T_SEQ 2048
#define NB    2
#define NH    16
#define HS    64
#define CEMB  1024
#define C3    3072
#define MTOT  (NB * T_SEQ)            // 4096
#define NQKV  (NB * NH * T_SEQ * HS)  // 4,194,304

// ---------------- device scratch: EXACTLY 64 MiB (proven-safe budget) -----
__device__ __align__(16) __nv_bfloat16 g_q_hi[NQKV];   // also W2_hi scratch post-attn
__device__ __align__(16) __nv_bfloat16 g_q_lo[NQKV];   // also W2_lo scratch post-attn
__device__ __align__(16) __nv_bfloat16 g_k_hi[NQKV];
__device__ __align__(16) __nv_bfloat16 g_k_lo[NQKV];
__device__ __align__(16) __nv_bfloat16 g_v_hi[NQKV];
__device__ __align__(16) __nv_bfloat16 g_v_lo[NQKV];
// aliased: split-x during gemm0, attention output for gemm1
__device__ __align__(16) __nv_bfloat16 g_a_hi[MTOT * CEMB];
__device__ __align__(16) __nv_bfloat16 g_a_lo[MTOT * CEMB];
// W1 planes live in d_out (16 MiB harness buffer, dead until gemm1 epilogue).

// ============================================================================
// helpers
// ============================================================================
__device__ __forceinline__ uint32_t smem_u32(const void* p) {
    uint32_t a;
    asm("{ .reg .u64 t; cvta.to.shared.u64 t, %1; cvt.u32.u64 %0, t; }"
        : "=r"(a) : "l"(p));
    return a;
}
__device__ __forceinline__ void split2(float v, __nv_bfloat16& h, __nv_bfloat16& l) {
    h = __float2bfloat16(v);
    l = __float2bfloat16(v - __bfloat162float(h));
}
__device__ __forceinline__ uint32_t pack_hi(float a, float b) {
    __nv_bfloat162 t;
    t.x = __float2bfloat16(a);
    t.y = __float2bfloat16(b);
    return *(uint32_t*)&t;
}
__device__ __forceinline__ uint32_t pack_lo(float a, float b) {
    __nv_bfloat16 ha = __float2bfloat16(a);
    __nv_bfloat16 hb = __float2bfloat16(b);
    __nv_bfloat162 t;
    t.x = __float2bfloat16(a - __bfloat162float(ha));
    t.y = __float2bfloat16(b - __bfloat162float(hb));
    return *(uint32_t*)&t;
}
__device__ __forceinline__ void cp16(uint32_t d, const void* s) {
    asm volatile("cp.async.cg.shared.global [%0], [%1], 16;" :: "r"(d), "l"(s));
}
#define CP_COMMIT() asm volatile("cp.async.commit_group;" ::: "memory")
#define CP_WAIT1()  asm volatile("cp.async.wait_group 1;" ::: "memory")
#define CP_WAIT0()  asm volatile("cp.async.wait_group 0;" ::: "memory")

__device__ __forceinline__ void ldm_x4(uint32_t addr, uint32_t r[4]) {
    asm volatile("ldmatrix.sync.aligned.m8n8.x4.shared.b16 {%0,%1,%2,%3}, [%4];"
        : "=r"(r[0]), "=r"(r[1]), "=r"(r[2]), "=r"(r[3]) : "r"(addr));
}
__device__ __forceinline__ void ldm_x4t(uint32_t addr, uint32_t r[4]) {
    asm volatile("ldmatrix.sync.aligned.m8n8.x4.trans.shared.b16 {%0,%1,%2,%3}, [%4];"
        : "=r"(r[0]), "=r"(r[1]), "=r"(r[2]), "=r"(r[3]) : "r"(addr));
}
__device__ __forceinline__ void mma16816(float c[4], const uint32_t a[4],
                                         const uint32_t b[2]) {
    asm volatile(
        "mma.sync.aligned.m16n8k16.row.col.f32.bf16.bf16.f32 "
        "{%0,%1,%2,%3}, {%4,%5,%6,%7}, {%8,%9}, {%0,%1,%2,%3};"
        : "+f"(c[0]), "+f"(c[1]), "+f"(c[2]), "+f"(c[3])
        : "r"(a[0]), "r"(a[1]), "r"(a[2]), "r"(a[3]), "r"(b[0]), "r"(b[1]));
}

// ============================================================================
// split kernels
// ============================================================================
__device__ __forceinline__ void split_store(float4 v, __nv_bfloat16* hi,
                                            __nv_bfloat16* lo, int i) {
    __nv_bfloat16 h0, h1, h2, h3, l0, l1, l2, l3;
    split2(v.x, h0, l0); split2(v.y, h1, l1);
    split2(v.z, h2, l2); split2(v.w, h3, l3);
    __nv_bfloat162 a, b, c, d;
    a.x = h0; a.y = h1; b.x = h2; b.y = h3;
    c.x = l0; c.y = l1; d.x = l2; d.y = l3;
    ((__nv_bfloat162*)hi)[2 * i]     = a;
    ((__nv_bfloat162*)hi)[2 * i + 1] = b;
    ((__nv_bfloat162*)lo)[2 * i]     = c;
    ((__nv_bfloat162*)lo)[2 * i + 1] = d;
}
__global__ void __launch_bounds__(256)
k_split_x(const float4* __restrict__ x) {
    int i = blockIdx.x * 256 + threadIdx.x;
    split_store(x[i], g_a_hi, g_a_lo, i);
}
__global__ void __launch_bounds__(256)
k_split_dst(const float4* __restrict__ src, __nv_bfloat16* __restrict__ hi,
            __nv_bfloat16* __restrict__ lo) {
    int i = blockIdx.x * 256 + threadIdx.x;
    split_store(src[i], hi, lo, i);
}
__global__ void __launch_bounds__(256)
k_split_w2(const float4* __restrict__ Wo) {
    int i = blockIdx.x * 256 + threadIdx.x;
    split_store(Wo[i], g_q_hi, g_q_lo, i);   // q planes dead after attention
}

// ============================================================================
// warp-MMA bf16x3 GEMM (UNCHANGED from passing round-13): pre-split operands,
// pure cp.async fill, intra-CTA double buffering, 2 CTAs/SM. CTA 128x64, BK=64.
// ============================================================================
#define STAGE   55296
#define GEMM_SMEM (2 * STAGE)    // 110,592 B

__device__ __forceinline__ void gemm_issue(uint32_t st, int m0, int n0, int ko,
                                           const __nv_bfloat16* __restrict__ whi,
                                           const __nv_bfloat16* __restrict__ wlo,
                                           int N, int tid)
{
#pragma unroll
    for (int j = 0; j < 4; j++) {
        const int idx = tid + j * 256;      // 0..1023
        const int r = idx >> 3;
        const int c = idx & 7;
        const size_t go = (size_t)(m0 + r) * CEMB + ko + c * 8;
        const uint32_t so = (uint32_t)(r * 144 + c * 16);
        cp16(st + so, g_a_hi + go);
        cp16(st + 18432 + so, g_a_lo + go);
    }
#pragma unroll
    for (int j = 0; j < 2; j++) {
        const int idx = tid + j * 256;      // 0..511
        const int k = idx >> 3;
        const int c = idx & 7;
        const size_t go = (size_t)(ko + k) * N + n0 + c * 8;
        const uint32_t so = (uint32_t)(k * 144 + c * 16);
        cp16(st + 36864 + so, whi + go);
        cp16(st + 46080 + so, wlo + go);
    }
}

template <int MODE>
__global__ void __launch_bounds__(256, 2)
mma_gemm(const __nv_bfloat16* __restrict__ whi_p,
         const __nv_bfloat16* __restrict__ wlo_p,
         const float* __restrict__ bias, float* __restrict__ Cout, int N)
{
    extern __shared__ char smem[];
    const uint32_t sbase = smem_u32(smem);

    const int tid  = threadIdx.x;
    const int lane = tid & 31;
    const int wid  = tid >> 5;
    const int m0   = blockIdx.y * 128;
    const int n0   = blockIdx.x * 64;
    const int wm0  = (wid & 3) * 32;
    const int wn0  = (wid >> 2) * 32;

    const __nv_bfloat16* whi = (MODE == 0) ? whi_p : (const __nv_bfloat16*)g_q_hi;
    const __nv_bfloat16* wlo = (MODE == 0) ? wlo_p : (const __nv_bfloat16*)g_q_lo;

    float acc[2][4][4];
#pragma unroll
    for (int mt = 0; mt < 2; mt++)
#pragma unroll
        for (int nt = 0; nt < 4; nt++)
#pragma unroll
            for (int e = 0; e < 4; e++) acc[mt][nt][e] = 0.0f;

    const uint32_t a_off = (uint32_t)((wm0 + (lane & 15)) * 144 + (lane >> 4) * 16);
    const uint32_t b_off = (uint32_t)(36864 +
        (((lane >> 3) & 1) * 8 + (lane & 7)) * 144 + wn0 * 2 + (lane >> 4) * 16);

    gemm_issue(sbase, m0, n0, 0, whi, wlo, N, tid);
    CP_COMMIT();

    constexpr int NKT = CEMB / 64;   // 16
    for (int kt = 0; kt < NKT; kt++) {
        const uint32_t st = sbase + (uint32_t)(kt & 1) * STAGE;
        if (kt + 1 < NKT) {
            gemm_issue(sbase + (uint32_t)((kt + 1) & 1) * STAGE,
                       m0, n0, (kt + 1) * 64, whi, wlo, N, tid);
            CP_COMMIT();
            CP_WAIT1();
        } else {
            CP_WAIT0();
        }
        __syncthreads();

        const uint32_t aBase = st + a_off;
        const uint32_t bBase = st + b_off;
#pragma unroll
        for (int ks = 0; ks < 4; ks++) {
            uint32_t bhi[2][4], blo[2][4];
#pragma unroll
            for (int g = 0; g < 2; g++) {
                const uint32_t bd = bBase + (uint32_t)(ks * 16 * 144 + g * 32);
                ldm_x4t(bd, bhi[g]);
                ldm_x4t(bd + 9216, blo[g]);
            }
#pragma unroll
            for (int mt = 0; mt < 2; mt++) {
                uint32_t ahi[4], alo[4];
                const uint32_t ad = aBase + (uint32_t)(mt * 16 * 144 + ks * 32);
                ldm_x4(ad, ahi);
                ldm_x4(ad + 18432, alo);
#pragma unroll
                for (int g = 0; g < 2; g++)
#pragma unroll
                    for (int h2 = 0; h2 < 2; h2++) {
                        const int nt = g * 2 + h2;
                        mma16816(acc[mt][nt], ahi, &bhi[g][h2 * 2]);
                        mma16816(acc[mt][nt], alo, &bhi[g][h2 * 2]);
                        mma16816(acc[mt][nt], ahi, &blo[g][h2 * 2]);
                    }
            }
        }
        __syncthreads();
    }

    // ---------------- epilogue ----------------
#pragma unroll
    for (int mt = 0; mt < 2; mt++) {
        const int mrow = m0 + wm0 + mt * 16 + (lane >> 2);
#pragma unroll
        for (int nt = 0; nt < 4; nt++) {
            const int nb = n0 + wn0 + nt * 8 + (lane & 3) * 2;
            const float b0 = bias[nb], b1 = bias[nb + 1];
            const float* a = acc[mt][nt];
            if (MODE == 0) {
                const int hh = nb / 192;
                const int e  = nb - hh * 192;
                const int wh = e >> 6;
                const int d0 = e & 63;
                __nv_bfloat16* ah = (wh == 0) ? g_q_hi : (wh == 1) ? g_k_hi : g_v_hi;
                __nv_bfloat16* al = (wh == 0) ? g_q_lo : (wh == 1) ? g_k_lo : g_v_lo;
                const int bi = mrow >> 11;
                const int t  = mrow & (T_SEQ - 1);
                const size_t o0 = ((size_t)((bi * NH + hh) * T_SEQ + t)) * HS + d0;
                *(uint32_t*)(ah + o0) = pack_hi(a[0] + b0, a[1] + b1);
                *(uint32_t*)(al + o0) = pack_lo(a[0] + b0, a[1] + b1);
                const size_t o1 = o0 + (size_t)8 * HS;
                *(uint32_t*)(ah + o1) = pack_hi(a[2] + b0, a[3] + b1);
                *(uint32_t*)(al + o1) = pack_lo(a[2] + b0, a[3] + b1);
            } else {
                float* dst0 = Cout + (size_t)mrow * N + nb;
                *(float2*)dst0 = make_float2(a[0] + b0, a[1] + b1);
                float* dst1 = Cout + (size_t)(mrow + 8) * N + nb;
                *(float2*)dst1 = make_float2(a[2] + b0, a[3] + b1);
            }
        }
    }
}

// ============================================================================
// Causal flash attention v4: BKV=64, __launch_bounds__(256,2) -> 2 CTAs/SM
// (the ONLY change this round; round-13 attn: 220us, occ 12.5%, tensor 46.5%).
// smem: Q hi/lo (36,864) + 2 KV stages of 36,864 = 110,592 B/CTA; x2 = 216 KB.
// ============================================================================
#define KVSTAGE 36864
#define ATTN_SMEM (36864 + 2 * KVSTAGE)   // 110,592 B

__device__ __forceinline__ void issue_kv(uint32_t kvb, size_t go_base, int tid) {
#pragma unroll
    for (int j = 0; j < 2; j++) {
        const int idx = tid + j * 256;     // 0..511
        const int r = idx >> 3;            // 0..63
        const int c = idx & 7;
        const size_t go = go_base + (size_t)r * HS + c * 8;
        const uint32_t so = (uint32_t)(r * 144 + c * 16);
        cp16(kvb + so, g_k_hi + go);
        cp16(kvb +  9216 + so, g_k_lo + go);
        cp16(kvb + 18432 + so, g_v_hi + go);
        cp16(kvb + 27648 + so, g_v_lo + go);
    }
}

__global__ void __launch_bounds__(256, 2)
attn_mma(void)
{
    extern __shared__ char smem[];
    const uint32_t sbase = smem_u32(smem);
    const int tid  = threadIdx.x;
    const int lane = tid & 31;
    const int wid  = tid >> 5;

    const int qt = gridDim.x - 1 - blockIdx.x;   // heavy q-tiles first
    const int h  = blockIdx.y;
    const int b  = blockIdx.z;
    const int q0 = qt * 128;

    const size_t base  = (size_t)(b * NH + h) * T_SEQ * HS;
    const size_t qbase = base + (size_t)q0 * HS;

    // ---- Q fill (cp.async, both planes) + first KV stage ----
#pragma unroll
    for (int j = 0; j < 4; j++) {
        const int idx = tid + j * 256;
        const int r = idx >> 3;
        const int c = idx & 7;
        const size_t go = qbase + (size_t)r * HS + c * 8;
        const uint32_t so = (uint32_t)(r * 144 + c * 16);
        cp16(sbase + so, g_q_hi + go);
        cp16(sbase + 18432 + so, g_q_lo + go);
    }
    issue_kv(sbase + 36864, base, tid);
    CP_COMMIT();

    const uint32_t a_off = (uint32_t)((wid * 16 + (lane & 15)) * 144 + (lane >> 4) * 16);
    const uint32_t k_off = (uint32_t)(((((lane >> 4) << 3) + (lane & 7)) * 144) +
                                      ((lane >> 3) & 1) * 16);
    const uint32_t v_off = (uint32_t)(((((lane >> 3) & 1) * 8 + (lane & 7)) * 144) +
                                      (lane >> 4) * 16);
    const uint32_t aBase = sbase + a_off;

    float o[8][4];
#pragma unroll
    for (int nt = 0; nt < 8; nt++)
#pragma unroll
        for (int e = 0; e < 4; e++) o[nt][e] = 0.0f;
    float m0 = -1e30f, m1 = -1e30f, l0 = 0.0f, l1 = 0.0f;

    const int rloc0 = wid * 16 + (lane >> 2);   // 0..127
    const int rloc1 = rloc0 + 8;

    const int nkv = 2 * qt + 2;                 // 64-wide kv tiles
    for (int ktv = 0; ktv < nkv; ktv++) {
        const uint32_t kvb = sbase + 36864 + (uint32_t)(ktv & 1) * KVSTAGE;
        if (ktv + 1 < nkv) {
            issue_kv(sbase + 36864 + (uint32_t)((ktv + 1) & 1) * KVSTAGE,
                     base + (size_t)(ktv + 1) * 64 * HS, tid);
            CP_COMMIT();
            CP_WAIT1();
        } else {
            CP_WAIT0();
        }
        __syncthreads();

        const uint32_t kBase = kvb + k_off;
        const uint32_t vBase = kvb + 18432 + v_off;

        // ---- S = Q @ K^T  (8 n-tiles of 8 keys = 64 keys) ----
        float s[8][4];
#pragma unroll
        for (int nt = 0; nt < 8; nt++)
#pragma unroll
            for (int e = 0; e < 4; e++) s[nt][e] = 0.0f;

#pragma unroll
        for (int ks = 0; ks < 4; ks++) {
            uint32_t ahi[4], alo[4];
            ldm_x4(aBase + ks * 32, ahi);
            ldm_x4(aBase + 18432 + ks * 32, alo);
#pragma unroll
            for (int g = 0; g < 4; g++) {
                uint32_t kh[4], kl[4];
                const uint32_t kd = kBase + (uint32_t)(g * 16 * 144 + ks * 32);
                ldm_x4(kd, kh);
                ldm_x4(kd + 9216, kl);
#pragma unroll
                for (int h2 = 0; h2 < 2; h2++) {
                    const int nt = g * 2 + h2;
                    mma16816(s[nt], ahi, &kh[h2 * 2]);
                    mma16816(s[nt], alo, &kh[h2 * 2]);
                    mma16816(s[nt], ahi, &kl[h2 * 2]);
                }
            }
        }

        // ---- scale 1/sqrt(64); causal mask on the last two 64-tiles ----
#pragma unroll
        for (int nt = 0; nt < 8; nt++)
#pragma unroll
            for (int e = 0; e < 4; e++) s[nt][e] *= 0.125f;

        if (ktv >= 2 * qt) {
            const int off = (ktv - 2 * qt) * 64;    // 0 or 64
#pragma unroll
            for (int nt = 0; nt < 8; nt++) {
                const int c0 = off + nt * 8 + (lane & 3) * 2;
                const int c1 = c0 + 1;
                if (c0 > rloc0) s[nt][0] = -1e30f;
                if (c1 > rloc0) s[nt][1] = -1e30f;
                if (c0 > rloc1) s[nt][2] = -1e30f;
                if (c1 > rloc1) s[nt][3] = -1e30f;
            }
        }

        // ---- online softmax ----
        float mx0 = -1e30f, mx1 = -1e30f;
#pragma unroll
        for (int nt = 0; nt < 8; nt++) {
            mx0 = fmaxf(mx0, fmaxf(s[nt][0], s[nt][1]));
            mx1 = fmaxf(mx1, fmaxf(s[nt][2], s[nt][3]));
        }
        mx0 = fmaxf(mx0, __shfl_xor_sync(0xffffffffu, mx0, 1));
        mx0 = fmaxf(mx0, __shfl_xor_sync(0xffffffffu, mx0, 2));
        mx1 = fmaxf(mx1, __shfl_xor_sync(0xffffffffu, mx1, 1));
        mx1 = fmaxf(mx1, __shfl_xor_sync(0xffffffffu, mx1, 2));

        const float mn0 = fmaxf(m0, mx0);
        const float mn1 = fmaxf(m1, mx1);
        const float sc0 = __expf(m0 - mn0);
        const float sc1 = __expf(m1 - mn1);
        m0 = mn0; m1 = mn1;

        float ls0 = 0.0f, ls1 = 0.0f;
#pragma unroll
        for (int nt = 0; nt < 8; nt++) {
            s[nt][0] = __expf(s[nt][0] - mn0);
            s[nt][1] = __expf(s[nt][1] - mn0);
            s[nt][2] = __expf(s[nt][2] - mn1);
            s[nt][3] = __expf(s[nt][3] - mn1);
            ls0 += s[nt][0] + s[nt][1];
            ls1 += s[nt][2] + s[nt][3];
        }
        ls0 += __shfl_xor_sync(0xffffffffu, ls0, 1);
        ls0 += __shfl_xor_sync(0xffffffffu, ls0, 2);
        ls1 += __shfl_xor_sync(0xffffffffu, ls1, 1);
        ls1 += __shfl_xor_sync(0xffffffffu, ls1, 2);
        l0 = l0 * sc0 + ls0;
        l1 = l1 * sc1 + ls1;

#pragma unroll
        for (int nt = 0; nt < 8; nt++) {
            o[nt][0] *= sc0; o[nt][1] *= sc0;
            o[nt][2] *= sc1; o[nt][3] *= sc1;
        }

        // ---- O += P @ V  (4 kv-groups of 16) ----
#pragma unroll
        for (int ksv = 0; ksv < 4; ksv++) {
            const int nt0 = 2 * ksv, nt1 = 2 * ksv + 1;
            uint32_t ph[4], pl[4];
            ph[0] = pack_hi(s[nt0][0], s[nt0][1]);
            ph[1] = pack_hi(s[nt0][2], s[nt0][3]);
            ph[2] = pack_hi(s[nt1][0], s[nt1][1]);
            ph[3] = pack_hi(s[nt1][2], s[nt1][3]);
            pl[0] = pack_lo(s[nt0][0], s[nt0][1]);
            pl[1] = pack_lo(s[nt0][2], s[nt0][3]);
            pl[2] = pack_lo(s[nt1][0], s[nt1][1]);
            pl[3] = pack_lo(s[nt1][2], s[nt1][3]);
#pragma unroll
            for (int g = 0; g < 4; g++) {
                uint32_t vh[4], vl[4];
                const uint32_t vd = vBase + (uint32_t)(ksv * 16 * 144 + g * 32);
                ldm_x4t(vd, vh);
                ldm_x4t(vd + 9216, vl);
#pragma unroll
                for (int h2 = 0; h2 < 2; h2++) {
                    const int nt = g * 2 + h2;
                    mma16816(o[nt], ph, &vh[h2 * 2]);
                    mma16816(o[nt], pl, &vh[h2 * 2]);
                    mma16816(o[nt], ph, &vl[h2 * 2]);
                }
            }
        }
        __syncthreads();   // KV stage reads done before it is re-issued
    }

    // ---- epilogue: normalize, write split bf16 to g_a planes ----
    const float inv0 = 1.0f / l0;
    const float inv1 = 1.0f / l1;
    const int grow0 = q0 + rloc0;
    const int grow1 = q0 + rloc1;
#pragma unroll
    for (int nt = 0; nt < 8; nt++) {
        const int d = nt * 8 + (lane & 3) * 2;
        const size_t o0 = ((size_t)(b * T_SEQ + grow0)) * CEMB + h * HS + d;
        *(uint32_t*)(g_a_hi + o0) = pack_hi(o[nt][0] * inv0, o[nt][1] * inv0);
        *(uint32_t*)(g_a_lo + o0) = pack_lo(o[nt][0] * inv0, o[nt][1] * inv0);
        const size_t o1 = ((size_t)(b * T_SEQ + grow1)) * CEMB + h * HS + d;
        *(uint32_t*)(g_a_hi + o1) = pack_hi(o[nt][2] * inv1, o[nt][3] * inv1);
        *(uint32_t*)(g_a_lo + o1) = pack_lo(o[nt][2] * inv1, o[nt][3] * inv1);
    }
}

// ============================================================================
// launch
// ============================================================================
extern "C" void kernel_launch(void* const* d_in, const int* in_sizes, int n_in,
                              void* d_out, int out_size)
{
    const float* x    = (const float*)d_in[0];
    const float* Wqkv = (const float*)d_in[1];
    const float* bqkv = (const float*)d_in[2];
    const float* Wo   = (const float*)d_in[3];
    const float* bo   = (const float*)d_in[4];
    float* out = (float*)d_out;

    // W1 planes live inside d_out (16 MiB): hi at 0, lo at +6 MiB.
    __nv_bfloat16* w1hi = (__nv_bfloat16*)d_out;
    __nv_bfloat16* w1lo = w1hi + (size_t)CEMB * C3;

    cudaFuncSetAttribute(attn_mma, cudaFuncAttributeMaxDynamicSharedMemorySize, ATTN_SMEM);
    cudaFuncSetAttribute(mma_gemm<0>, cudaFuncAttributeMaxDynamicSharedMemorySize, GEMM_SMEM);
    cudaFuncSetAttribute(mma_gemm<1>, cudaFuncAttributeMaxDynamicSharedMemorySize, GEMM_SMEM);

    // 0) splits: x -> g_a planes; W1 -> d_out scratch planes
    k_split_x  <<<(MTOT * CEMB / 4) / 256, 256>>>((const float4*)x);
    k_split_dst<<<(CEMB * C3 / 4) / 256, 256>>>((const float4*)Wqkv, w1hi, w1lo);

    // 1) QKV projection -> split g_q/g_k/g_v planes
    mma_gemm<0><<<dim3(C3 / 64, MTOT / 128), 256, GEMM_SMEM>>>(w1hi, w1lo,
                                                               bqkv, nullptr, C3);

    // 2) causal flash attention -> split g_a planes
    attn_mma<<<dim3(T_SEQ / 128, NH, NB), 256, ATTN_SMEM>>>();

    // 3) W2 split into g_q plane space (dead after attention)
    k_split_w2<<<(CEMB * CEMB / 4) / 256, 256>>>((const float4*)Wo);

    // 4) output projection -> d_out (overwrites W1 scratch completely)
    mma_gemm<1><<<dim3(CEMB / 64, MTOT / 128), 256, GEMM_SMEM>>>(nullptr, nullptr,
                                                                 bo, out, CEMB);
}

// round 16
// speedup vs baseline: 1.0572x; 1.0572x over previous
#include <cuda_runtime.h>
#include <cuda_bf16.h>
#include <cstdint>

// ---------------- problem constants ----------------
#define T_SEQ 2048
#define NB    2
#define NH    16
#define HS    64
#define CEMB  1024
#define C3    3072
#define MTOT  (NB * T_SEQ)            // 4096
#define NQKV  (NB * NH * T_SEQ * HS)  // 4,194,304
#define QSCALE 0.18033688011112042f   // 0.125 * log2(e)

// ---------------- device scratch: EXACTLY 64 MiB (proven-safe budget) -----
__device__ __align__(16) __nv_bfloat16 g_q_hi[NQKV];   // also W2_hi scratch post-attn
__device__ __align__(16) __nv_bfloat16 g_q_lo[NQKV];   // also W2_lo scratch post-attn
__device__ __align__(16) __nv_bfloat16 g_k_hi[NQKV];
__device__ __align__(16) __nv_bfloat16 g_k_lo[NQKV];
__device__ __align__(16) __nv_bfloat16 g_v_hi[NQKV];
__device__ __align__(16) __nv_bfloat16 g_v_lo[NQKV];
// aliased: split-x during gemm0, attention output for gemm1
__device__ __align__(16) __nv_bfloat16 g_a_hi[MTOT * CEMB];
__device__ __align__(16) __nv_bfloat16 g_a_lo[MTOT * CEMB];
// W1 planes live in d_out (16 MiB harness buffer, dead until gemm1 epilogue).

// ============================================================================
// helpers
// ============================================================================
__device__ __forceinline__ uint32_t smem_u32(const void* p) {
    uint32_t a;
    asm("{ .reg .u64 t; cvta.to.shared.u64 t, %1; cvt.u32.u64 %0, t; }"
        : "=r"(a) : "l"(p));
    return a;
}
__device__ __forceinline__ void split2(float v, __nv_bfloat16& h, __nv_bfloat16& l) {
    h = __float2bfloat16(v);
    l = __float2bfloat16(v - __bfloat162float(h));
}
__device__ __forceinline__ uint32_t pack_hi(float a, float b) {
    __nv_bfloat162 t;
    t.x = __float2bfloat16(a);
    t.y = __float2bfloat16(b);
    return *(uint32_t*)&t;
}
__device__ __forceinline__ uint32_t pack_lo(float a, float b) {
    __nv_bfloat16 ha = __float2bfloat16(a);
    __nv_bfloat16 hb = __float2bfloat16(b);
    __nv_bfloat162 t;
    t.x = __float2bfloat16(a - __bfloat162float(ha));
    t.y = __float2bfloat16(b - __bfloat162float(hb));
    return *(uint32_t*)&t;
}
__device__ __forceinline__ void cp16(uint32_t d, const void* s) {
    asm volatile("cp.async.cg.shared.global [%0], [%1], 16;" :: "r"(d), "l"(s));
}
#define CP_COMMIT() asm volatile("cp.async.commit_group;" ::: "memory")
#define CP_WAIT1()  asm volatile("cp.async.wait_group 1;" ::: "memory")
#define CP_WAIT0()  asm volatile("cp.async.wait_group 0;" ::: "memory")

__device__ __forceinline__ void ldm_x4(uint32_t addr, uint32_t r[4]) {
    asm volatile("ldmatrix.sync.aligned.m8n8.x4.shared.b16 {%0,%1,%2,%3}, [%4];"
        : "=r"(r[0]), "=r"(r[1]), "=r"(r[2]), "=r"(r[3]) : "r"(addr));
}
__device__ __forceinline__ void ldm_x4t(uint32_t addr, uint32_t r[4]) {
    asm volatile("ldmatrix.sync.aligned.m8n8.x4.trans.shared.b16 {%0,%1,%2,%3}, [%4];"
        : "=r"(r[0]), "=r"(r[1]), "=r"(r[2]), "=r"(r[3]) : "r"(addr));
}
__device__ __forceinline__ void mma16816(float c[4], const uint32_t a[4],
                                         const uint32_t b[2]) {
    asm volatile(
        "mma.sync.aligned.m16n8k16.row.col.f32.bf16.bf16.f32 "
        "{%0,%1,%2,%3}, {%4,%5,%6,%7}, {%8,%9}, {%0,%1,%2,%3};"
        : "+f"(c[0]), "+f"(c[1]), "+f"(c[2]), "+f"(c[3])
        : "r"(a[0]), "r"(a[1]), "r"(a[2]), "r"(a[3]), "r"(b[0]), "r"(b[1]));
}

// ============================================================================
// split kernels
// ============================================================================
__device__ __forceinline__ void split_store(float4 v, __nv_bfloat16* hi,
                                            __nv_bfloat16* lo, int i) {
    __nv_bfloat16 h0, h1, h2, h3, l0, l1, l2, l3;
    split2(v.x, h0, l0); split2(v.y, h1, l1);
    split2(v.z, h2, l2); split2(v.w, h3, l3);
    __nv_bfloat162 a, b, c, d;
    a.x = h0; a.y = h1; b.x = h2; b.y = h3;
    c.x = l0; c.y = l1; d.x = l2; d.y = l3;
    ((__nv_bfloat162*)hi)[2 * i]     = a;
    ((__nv_bfloat162*)hi)[2 * i + 1] = b;
    ((__nv_bfloat162*)lo)[2 * i]     = c;
    ((__nv_bfloat162*)lo)[2 * i + 1] = d;
}
__global__ void __launch_bounds__(256)
k_split_x(const float4* __restrict__ x) {
    int i = blockIdx.x * 256 + threadIdx.x;
    split_store(x[i], g_a_hi, g_a_lo, i);
}
__global__ void __launch_bounds__(256)
k_split_dst(const float4* __restrict__ src, __nv_bfloat16* __restrict__ hi,
            __nv_bfloat16* __restrict__ lo) {
    int i = blockIdx.x * 256 + threadIdx.x;
    split_store(src[i], hi, lo, i);
}
__global__ void __launch_bounds__(256)
k_split_w2(const float4* __restrict__ Wo) {
    int i = blockIdx.x * 256 + threadIdx.x;
    split_store(Wo[i], g_q_hi, g_q_lo, i);   // q planes dead after attention
}

// ============================================================================
// warp-MMA bf16x3 GEMM (round-13 proven; one change: MODE 0 scales Q by
// QSCALE = 0.125*log2(e) at pack time so attention can use exp2f directly).
// ============================================================================
#define STAGE   55296
#define GEMM_SMEM (2 * STAGE)    // 110,592 B

__device__ __forceinline__ void gemm_issue(uint32_t st, int m0, int n0, int ko,
                                           const __nv_bfloat16* __restrict__ whi,
                                           const __nv_bfloat16* __restrict__ wlo,
                                           int N, int tid)
{
#pragma unroll
    for (int j = 0; j < 4; j++) {
        const int idx = tid + j * 256;      // 0..1023
        const int r = idx >> 3;
        const int c = idx & 7;
        const size_t go = (size_t)(m0 + r) * CEMB + ko + c * 8;
        const uint32_t so = (uint32_t)(r * 144 + c * 16);
        cp16(st + so, g_a_hi + go);
        cp16(st + 18432 + so, g_a_lo + go);
    }
#pragma unroll
    for (int j = 0; j < 2; j++) {
        const int idx = tid + j * 256;      // 0..511
        const int k = idx >> 3;
        const int c = idx & 7;
        const size_t go = (size_t)(ko + k) * N + n0 + c * 8;
        const uint32_t so = (uint32_t)(k * 144 + c * 16);
        cp16(st + 36864 + so, whi + go);
        cp16(st + 46080 + so, wlo + go);
    }
}

template <int MODE>
__global__ void __launch_bounds__(256, 2)
mma_gemm(const __nv_bfloat16* __restrict__ whi_p,
         const __nv_bfloat16* __restrict__ wlo_p,
         const float* __restrict__ bias, float* __restrict__ Cout, int N)
{
    extern __shared__ char smem[];
    const uint32_t sbase = smem_u32(smem);

    const int tid  = threadIdx.x;
    const int lane = tid & 31;
    const int wid  = tid >> 5;
    const int m0   = blockIdx.y * 128;
    const int n0   = blockIdx.x * 64;
    const int wm0  = (wid & 3) * 32;
    const int wn0  = (wid >> 2) * 32;

    const __nv_bfloat16* whi = (MODE == 0) ? whi_p : (const __nv_bfloat16*)g_q_hi;
    const __nv_bfloat16* wlo = (MODE == 0) ? wlo_p : (const __nv_bfloat16*)g_q_lo;

    float acc[2][4][4];
#pragma unroll
    for (int mt = 0; mt < 2; mt++)
#pragma unroll
        for (int nt = 0; nt < 4; nt++)
#pragma unroll
            for (int e = 0; e < 4; e++) acc[mt][nt][e] = 0.0f;

    const uint32_t a_off = (uint32_t)((wm0 + (lane & 15)) * 144 + (lane >> 4) * 16);
    const uint32_t b_off = (uint32_t)(36864 +
        (((lane >> 3) & 1) * 8 + (lane & 7)) * 144 + wn0 * 2 + (lane >> 4) * 16);

    gemm_issue(sbase, m0, n0, 0, whi, wlo, N, tid);
    CP_COMMIT();

    constexpr int NKT = CEMB / 64;   // 16
    for (int kt = 0; kt < NKT; kt++) {
        const uint32_t st = sbase + (uint32_t)(kt & 1) * STAGE;
        if (kt + 1 < NKT) {
            gemm_issue(sbase + (uint32_t)((kt + 1) & 1) * STAGE,
                       m0, n0, (kt + 1) * 64, whi, wlo, N, tid);
            CP_COMMIT();
            CP_WAIT1();
        } else {
            CP_WAIT0();
        }
        __syncthreads();

        const uint32_t aBase = st + a_off;
        const uint32_t bBase = st + b_off;
#pragma unroll
        for (int ks = 0; ks < 4; ks++) {
            uint32_t bhi[2][4], blo[2][4];
#pragma unroll
            for (int g = 0; g < 2; g++) {
                const uint32_t bd = bBase + (uint32_t)(ks * 16 * 144 + g * 32);
                ldm_x4t(bd, bhi[g]);
                ldm_x4t(bd + 9216, blo[g]);
            }
#pragma unroll
            for (int mt = 0; mt < 2; mt++) {
                uint32_t ahi[4], alo[4];
                const uint32_t ad = aBase + (uint32_t)(mt * 16 * 144 + ks * 32);
                ldm_x4(ad, ahi);
                ldm_x4(ad + 18432, alo);
#pragma unroll
                for (int g = 0; g < 2; g++)
#pragma unroll
                    for (int h2 = 0; h2 < 2; h2++) {
                        const int nt = g * 2 + h2;
                        mma16816(acc[mt][nt], ahi, &bhi[g][h2 * 2]);
                        mma16816(acc[mt][nt], alo, &bhi[g][h2 * 2]);
                        mma16816(acc[mt][nt], ahi, &blo[g][h2 * 2]);
                    }
            }
        }
        __syncthreads();
    }

    // ---------------- epilogue ----------------
#pragma unroll
    for (int mt = 0; mt < 2; mt++) {
        const int mrow = m0 + wm0 + mt * 16 + (lane >> 2);
#pragma unroll
        for (int nt = 0; nt < 4; nt++) {
            const int nb = n0 + wn0 + nt * 8 + (lane & 3) * 2;
            const float b0 = bias[nb], b1 = bias[nb + 1];
            const float* a = acc[mt][nt];
            if (MODE == 0) {
                const int hh = nb / 192;
                const int e  = nb - hh * 192;
                const int wh = e >> 6;
                const int d0 = e & 63;
                __nv_bfloat16* ah = (wh == 0) ? g_q_hi : (wh == 1) ? g_k_hi : g_v_hi;
                __nv_bfloat16* al = (wh == 0) ? g_q_lo : (wh == 1) ? g_k_lo : g_v_lo;
                const float scl = (wh == 0) ? QSCALE : 1.0f;   // fold 1/8*log2e into Q
                const int bi = mrow >> 11;
                const int t  = mrow & (T_SEQ - 1);
                const size_t o0 = ((size_t)((bi * NH + hh) * T_SEQ + t)) * HS + d0;
                *(uint32_t*)(ah + o0) = pack_hi((a[0] + b0) * scl, (a[1] + b1) * scl);
                *(uint32_t*)(al + o0) = pack_lo((a[0] + b0) * scl, (a[1] + b1) * scl);
                const size_t o1 = o0 + (size_t)8 * HS;
                *(uint32_t*)(ah + o1) = pack_hi((a[2] + b0) * scl, (a[3] + b1) * scl);
                *(uint32_t*)(al + o1) = pack_lo((a[2] + b0) * scl, (a[3] + b1) * scl);
            } else {
                float* dst0 = Cout + (size_t)mrow * N + nb;
                *(float2*)dst0 = make_float2(a[0] + b0, a[1] + b1);
                float* dst1 = Cout + (size_t)(mrow + 8) * N + nb;
                *(float2*)dst1 = make_float2(a[2] + b0, a[3] + b1);
            }
        }
    }
}

// ============================================================================
// Causal flash attention: round-13 structure (BKV=128, occ 1) with two cuts:
//   - softmax in exp2 domain (scale pre-folded into Q) -> no scale loop,
//     no implicit log2e mul inside exp
//   - ONE __syncthreads per KV iteration: [wait0 -> sync -> issue kt+1 ->
//     compute kt].  Prefetch of KV(kt+1) still overlaps compute kt; the
//     top-of-loop sync guarantees all warps finished reading stage (kt+1)&1
//     (used in iter kt-1) before it is refilled.
// ============================================================================
#define KVBUF (4 * 18432)
#define ATTN_SMEM (2 * 18432 + 2 * KVBUF)   // 184,320 B

__device__ __forceinline__ void issue_kv(uint32_t kvb, size_t go_base, int tid) {
#pragma unroll
    for (int j = 0; j < 4; j++) {
        const int idx = tid + j * 256;
        const int r = idx >> 3;
        const int c = idx & 7;
        const size_t go = go_base + (size_t)r * HS + c * 8;
        const uint32_t so = (uint32_t)(r * 144 + c * 16);
        cp16(kvb + 0 * 18432 + so, g_k_hi + go);
        cp16(kvb + 1 * 18432 + so, g_k_lo + go);
        cp16(kvb + 2 * 18432 + so, g_v_hi + go);
        cp16(kvb + 3 * 18432 + so, g_v_lo + go);
    }
}

__global__ void __launch_bounds__(256, 1)
attn_mma(void)
{
    extern __shared__ char smem[];
    const uint32_t sbase = smem_u32(smem);
    const int tid  = threadIdx.x;
    const int lane = tid & 31;
    const int wid  = tid >> 5;

    const int qt = gridDim.x - 1 - blockIdx.x;
    const int h  = blockIdx.y;
    const int b  = blockIdx.z;
    const int q0 = qt * 128;

    const size_t base  = (size_t)(b * NH + h) * T_SEQ * HS;
    const size_t qbase = base + (size_t)q0 * HS;

#pragma unroll
    for (int j = 0; j < 4; j++) {
        const int idx = tid + j * 256;
        const int r = idx >> 3;
        const int c = idx & 7;
        const size_t go = qbase + (size_t)r * HS + c * 8;
        const uint32_t so = (uint32_t)(r * 144 + c * 16);
        cp16(sbase + so, g_q_hi + go);
        cp16(sbase + 18432 + so, g_q_lo + go);
    }
    issue_kv(sbase + 2 * 18432, base, tid);
    CP_COMMIT();

    const uint32_t a_off = (uint32_t)((wid * 16 + (lane & 15)) * 144 + (lane >> 4) * 16);
    const uint32_t k_off = (uint32_t)(((((lane >> 4) << 3) + (lane & 7)) * 144) +
                                      ((lane >> 3) & 1) * 16);
    const uint32_t v_off = (uint32_t)(((((lane >> 3) & 1) * 8 + (lane & 7)) * 144) +
                                      (lane >> 4) * 16);
    const uint32_t aBase = sbase + a_off;

    float o[8][4];
#pragma unroll
    for (int nt = 0; nt < 8; nt++)
#pragma unroll
        for (int e = 0; e < 4; e++) o[nt][e] = 0.0f;
    float m0 = -1e30f, m1 = -1e30f, l0 = 0.0f, l1 = 0.0f;

    const int rloc0 = wid * 16 + (lane >> 2);
    const int rloc1 = rloc0 + 8;

    for (int kt = 0; kt <= qt; kt++) {
        const uint32_t kvb = sbase + 2 * 18432 + (uint32_t)(kt & 1) * KVBUF;
        CP_WAIT0();          // KV kt (issued last iteration) complete
        __syncthreads();     // data visible to all warps; stage (kt+1)&1 free
        if (kt < qt) {
            issue_kv(sbase + 2 * 18432 + (uint32_t)((kt + 1) & 1) * KVBUF,
                     base + (size_t)(kt + 1) * 128 * HS, tid);
            CP_COMMIT();
        }

        const uint32_t kBase = kvb + k_off;
        const uint32_t vBase = kvb + 2 * 18432 + v_off;

        // ---- S = Q @ K^T (Q pre-scaled by 0.125*log2e) ----
        float s[16][4];
#pragma unroll
        for (int nt = 0; nt < 16; nt++)
#pragma unroll
            for (int e = 0; e < 4; e++) s[nt][e] = 0.0f;

#pragma unroll
        for (int ks = 0; ks < 4; ks++) {
            uint32_t ahi[4], alo[4];
            ldm_x4(aBase + ks * 32, ahi);
            ldm_x4(aBase + 18432 + ks * 32, alo);
#pragma unroll
            for (int g = 0; g < 8; g++) {
                uint32_t kh[4], kl[4];
                const uint32_t kd = kBase + (uint32_t)(g * 16 * 144 + ks * 32);
                ldm_x4(kd, kh);
                ldm_x4(kd + 18432, kl);
#pragma unroll
                for (int h2 = 0; h2 < 2; h2++) {
                    const int nt = g * 2 + h2;
                    mma16816(s[nt], ahi, &kh[h2 * 2]);
                    mma16816(s[nt], alo, &kh[h2 * 2]);
                    mma16816(s[nt], ahi, &kl[h2 * 2]);
                }
            }
        }

        if (kt == qt) {
#pragma unroll
            for (int nt = 0; nt < 16; nt++) {
                const int c0 = nt * 8 + (lane & 3) * 2;
                const int c1 = c0 + 1;
                if (c0 > rloc0) s[nt][0] = -1e30f;
                if (c1 > rloc0) s[nt][1] = -1e30f;
                if (c0 > rloc1) s[nt][2] = -1e30f;
                if (c1 > rloc1) s[nt][3] = -1e30f;
            }
        }

        // ---- online softmax in exp2 domain ----
        float mx0 = -1e30f, mx1 = -1e30f;
#pragma unroll
        for (int nt = 0; nt < 16; nt++) {
            mx0 = fmaxf(mx0, fmaxf(s[nt][0], s[nt][1]));
            mx1 = fmaxf(mx1, fmaxf(s[nt][2], s[nt][3]));
        }
        mx0 = fmaxf(mx0, __shfl_xor_sync(0xffffffffu, mx0, 1));
        mx0 = fmaxf(mx0, __shfl_xor_sync(0xffffffffu, mx0, 2));
        mx1 = fmaxf(mx1, __shfl_xor_sync(0xffffffffu, mx1, 1));
        mx1 = fmaxf(mx1, __shfl_xor_sync(0xffffffffu, mx1, 2));

        const float mn0 = fmaxf(m0, mx0);
        const float mn1 = fmaxf(m1, mx1);
        const float sc0 = exp2f(m0 - mn0);
        const float sc1 = exp2f(m1 - mn1);
        m0 = mn0; m1 = mn1;

        float ls0 = 0.0f, ls1 = 0.0f;
#pragma unroll
        for (int nt = 0; nt < 16; nt++) {
            s[nt][0] = exp2f(s[nt][0] - mn0);
            s[nt][1] = exp2f(s[nt][1] - mn0);
            s[nt][2] = exp2f(s[nt][2] - mn1);
            s[nt][3] = exp2f(s[nt][3] - mn1);
            ls0 += s[nt][0] + s[nt][1];
            ls1 += s[nt][2] + s[nt][3];
        }
        ls0 += __shfl_xor_sync(0xffffffffu, ls0, 1);
        ls0 += __shfl_xor_sync(0xffffffffu, ls0, 2);
        ls1 += __shfl_xor_sync(0xffffffffu, ls1, 1);
        ls1 += __shfl_xor_sync(0xffffffffu, ls1, 2);
        l0 = l0 * sc0 + ls0;
        l1 = l1 * sc1 + ls1;

#pragma unroll
        for (int nt = 0; nt < 8; nt++) {
            o[nt][0] *= sc0; o[nt][1] *= sc0;
            o[nt][2] *= sc1; o[nt][3] *= sc1;
        }

        // ---- O += P @ V ----
#pragma unroll
        for (int ksv = 0; ksv < 8; ksv++) {
            const int nt0 = 2 * ksv, nt1 = 2 * ksv + 1;
            uint32_t ph[4], pl[4];
            ph[0] = pack_hi(s[nt0][0], s[nt0][1]);
            ph[1] = pack_hi(s[nt0][2], s[nt0][3]);
            ph[2] = pack_hi(s[nt1][0], s[nt1][1]);
            ph[3] = pack_hi(s[nt1][2], s[nt1][3]);
            pl[0] = pack_lo(s[nt0][0], s[nt0][1]);
            pl[1] = pack_lo(s[nt0][2], s[nt0][3]);
            pl[2] = pack_lo(s[nt1][0], s[nt1][1]);
            pl[3] = pack_lo(s[nt1][2], s[nt1][3]);
#pragma unroll
            for (int g = 0; g < 4; g++) {
                uint32_t vh[4], vl[4];
                const uint32_t vd = vBase + (uint32_t)(ksv * 16 * 144 + g * 32);
                ldm_x4t(vd, vh);
                ldm_x4t(vd + 18432, vl);
#pragma unroll
                for (int h2 = 0; h2 < 2; h2++) {
                    const int nt = g * 2 + h2;
                    mma16816(o[nt], ph, &vh[h2 * 2]);
                    mma16816(o[nt], pl, &vh[h2 * 2]);
                    mma16816(o[nt], ph, &vl[h2 * 2]);
                }
            }
        }
    }

    // ---- epilogue: normalize, write split bf16 to g_a planes ----
    const float inv0 = 1.0f / l0;
    const float inv1 = 1.0f / l1;
    const int grow0 = q0 + rloc0;
    const int grow1 = q0 + rloc1;
#pragma unroll
    for (int nt = 0; nt < 8; nt++) {
        const int d = nt * 8 + (lane & 3) * 2;
        const size_t o0 = ((size_t)(b * T_SEQ + grow0)) * CEMB + h * HS + d;
        *(uint32_t*)(g_a_hi + o0) = pack_hi(o[nt][0] * inv0, o[nt][1] * inv0);
        *(uint32_t*)(g_a_lo + o0) = pack_lo(o[nt][0] * inv0, o[nt][1] * inv0);
        const size_t o1 = ((size_t)(b * T_SEQ + grow1)) * CEMB + h * HS + d;
        *(uint32_t*)(g_a_hi + o1) = pack_hi(o[nt][2] * inv1, o[nt][3] * inv1);
        *(uint32_t*)(g_a_lo + o1) = pack_lo(o[nt][2] * inv1, o[nt][3] * inv1);
    }
}

// ============================================================================
// launch
// ============================================================================
extern "C" void kernel_launch(void* const* d_in, const int* in_sizes, int n_in,
                              void* d_out, int out_size)
{
    const float* x    = (const float*)d_in[0];
    const float* Wqkv = (const float*)d_in[1];
    const float* bqkv = (const float*)d_in[2];
    const float* Wo   = (const float*)d_in[3];
    const float* bo   = (const float*)d_in[4];
    float* out = (float*)d_out;

    // W1 planes live inside d_out (16 MiB): hi at 0, lo at +6 MiB.
    __nv_bfloat16* w1hi = (__nv_bfloat16*)d_out;
    __nv_bfloat16* w1lo = w1hi + (size_t)CEMB * C3;

    cudaFuncSetAttribute(attn_mma, cudaFuncAttributeMaxDynamicSharedMemorySize, ATTN_SMEM);
    cudaFuncSetAttribute(mma_gemm<0>, cudaFuncAttributeMaxDynamicSharedMemorySize, GEMM_SMEM);
    cudaFuncSetAttribute(mma_gemm<1>, cudaFuncAttributeMaxDynamicSharedMemorySize, GEMM_SMEM);

    // 0) splits: x -> g_a planes; W1 -> d_out scratch planes
    k_split_x  <<<(MTOT * CEMB / 4) / 256, 256>>>((const float4*)x);
    k_split_dst<<<(CEMB * C3 / 4) / 256, 256>>>((const float4*)Wqkv, w1hi, w1lo);

    // 1) QKV projection -> split g_q/g_k/g_v planes (Q pre-scaled)
    mma_gemm<0><<<dim3(C3 / 64, MTOT / 128), 256, GEMM_SMEM>>>(w1hi, w1lo,
                                                               bqkv, nullptr, C3);

    // 2) causal flash attention -> split g_a planes
    attn_mma<<<dim3(T_SEQ / 128, NH, NB), 256, ATTN_SMEM>>>();

    // 3) W2 split into g_q plane space (dead after attention)
    k_split_w2<<<(CEMB * CEMB / 4) / 256, 256>>>((const float4*)Wo);

    // 4) output projection -> d_out (overwrites W1 scratch completely)
    mma_gemm<1><<<dim3(CEMB / 64, MTOT / 128), 256, GEMM_SMEM>>>(nullptr, nullptr,
                                                                 bo, out, CEMB);
}